// round 1
// baseline (speedup 1.0000x reference)
#include <cuda_runtime.h>
#include <cstddef>

#define NN   100000
#define EE   800000
#define DD   64
#define GG   64
#define OUTD 32
#define FF   61
#define NLAY 4

// ---- device scratch (no runtime allocation allowed) ----
__device__ float g_h[NN * DD];     // current node features
__device__ float g_agg[NN * DD];   // per-layer message aggregation
__device__ float g_d2[EE];         // squared edge distances (constant across layers)
__device__ float g_pool[GG * OUTD];
__device__ float g_cnt[GG];

__device__ __forceinline__ void red_add_v4(float* addr, float a, float b, float c, float d) {
    asm volatile("red.global.add.v4.f32 [%0], {%1,%2,%3,%4};"
                 :: "l"(addr), "f"(a), "f"(b), "f"(c), "f"(d) : "memory");
}
__device__ __forceinline__ void red_add_v2(float* addr, float a, float b) {
    asm volatile("red.global.add.v2.f32 [%0], {%1,%2};"
                 :: "l"(addr), "f"(a), "f"(b) : "memory");
}

// ---- squared pairwise distances per edge ----
__global__ void k_d2(const float* __restrict__ pos, const int* __restrict__ ei) {
    int e = blockIdx.x * blockDim.x + threadIdx.x;
    if (e >= EE) return;
    int s = ei[e], d = ei[EE + e];
    float dx = pos[s * 3 + 0] - pos[d * 3 + 0];
    float dy = pos[s * 3 + 1] - pos[d * 3 + 1];
    float dz = pos[s * 3 + 2] - pos[d * 3 + 2];
    g_d2[e] = dx * dx + dy * dy + dz * dz;
}

// ---- zero helpers ----
__global__ void k_zero_agg() {
    int i = blockIdx.x * blockDim.x + threadIdx.x;
    if (i * 4 < NN * DD) {
        float4 z = make_float4(0.f, 0.f, 0.f, 0.f);
        *(float4*)&g_agg[i * 4] = z;
    }
}
__global__ void k_zero_pool() {
    int i = threadIdx.x;
    for (int j = i; j < GG * OUTD; j += 256) g_pool[j] = 0.f;
    if (i < GG) g_cnt[i] = 0.f;
}

// ---- input embedding + t1 input projection: h = [pos, emb[z]] @ Win ----
__global__ __launch_bounds__(256) void k_init(const float* __restrict__ pos,
                                              const int* __restrict__ z,
                                              const float* __restrict__ emb,
                                              const float* __restrict__ Win) {
    __shared__ float Ws[DD * DD];
    __shared__ float xs[64 * 68];
    int tid = threadIdx.x;
    for (int i = tid; i < DD * DD; i += 256) Ws[i] = Win[i];
    int base = blockIdx.x * 64;
    int warp = tid >> 5, lane = tid & 31;
    for (int t = 0; t < 8; t++) {
        int r = warp * 8 + t;
        int g = base + r;
        float v0 = 0.f, v1 = 0.f;
        if (g < NN) {
            int zi = z[g];
            v0 = (lane < 3) ? pos[g * 3 + lane] : emb[zi * FF + lane - 3];
            v1 = emb[zi * FF + lane + 29];
        }
        xs[r * 68 + lane] = v0;
        xs[r * 68 + lane + 32] = v1;
    }
    __syncthreads();
    int tr = tid >> 4, tc = tid & 15, c0 = tc * 4;
    float acc[4][4];
#pragma unroll
    for (int i = 0; i < 4; i++)
#pragma unroll
        for (int j = 0; j < 4; j++) acc[i][j] = 0.f;
    for (int k = 0; k < DD; k++) {
        float4 w = *(const float4*)&Ws[k * DD + c0];
#pragma unroll
        for (int i = 0; i < 4; i++) {
            float xv = xs[(tr + 16 * i) * 68 + k];
            acc[i][0] += xv * w.x; acc[i][1] += xv * w.y;
            acc[i][2] += xv * w.z; acc[i][3] += xv * w.w;
        }
    }
#pragma unroll
    for (int i = 0; i < 4; i++) {
        int g = base + tr + 16 * i;
        if (g < NN) {
            float4 o = make_float4(acc[i][0], acc[i][1], acc[i][2], acc[i][3]);
            *(float4*)&g_h[(size_t)g * DD + c0] = o;
        }
    }
}

// ---- t2 input projection: h = relu(h) @ Win (in-place, per-row independent) ----
__global__ __launch_bounds__(256) void k_proj(const float* __restrict__ Win) {
    __shared__ float Ws[DD * DD];
    __shared__ float xs[64 * 68];
    int tid = threadIdx.x;
    for (int i = tid; i < DD * DD; i += 256) Ws[i] = Win[i];
    int base = blockIdx.x * 64;
    int warp = tid >> 5, lane = tid & 31;
    for (int t = 0; t < 8; t++) {
        int r = warp * 8 + t;
        int g = base + r;
        float v0 = 0.f, v1 = 0.f;
        if (g < NN) {
            v0 = fmaxf(g_h[(size_t)g * DD + lane], 0.f);
            v1 = fmaxf(g_h[(size_t)g * DD + lane + 32], 0.f);
        }
        xs[r * 68 + lane] = v0;
        xs[r * 68 + lane + 32] = v1;
    }
    __syncthreads();
    int tr = tid >> 4, tc = tid & 15, c0 = tc * 4;
    float acc[4][4];
#pragma unroll
    for (int i = 0; i < 4; i++)
#pragma unroll
        for (int j = 0; j < 4; j++) acc[i][j] = 0.f;
    for (int k = 0; k < DD; k++) {
        float4 w = *(const float4*)&Ws[k * DD + c0];
#pragma unroll
        for (int i = 0; i < 4; i++) {
            float xv = xs[(tr + 16 * i) * 68 + k];
            acc[i][0] += xv * w.x; acc[i][1] += xv * w.y;
            acc[i][2] += xv * w.z; acc[i][3] += xv * w.w;
        }
    }
#pragma unroll
    for (int i = 0; i < 4; i++) {
        int g = base + tr + 16 * i;
        if (g < NN) {
            float4 o = make_float4(acc[i][0], acc[i][1], acc[i][2], acc[i][3]);
            *(float4*)&g_h[(size_t)g * DD + c0] = o;
        }
    }
}

// ---- edge MLP + scatter: agg[dst] += relu([h[src],h[dst],d2]@W1+b1)@W2+b2 ----
// 128 edges/block, 256 threads, thread tile 8 rows x 4 cols (rows strided by 16).
#define EDGE_SMEM (38080 * 4 + 128 * 4)
__global__ __launch_bounds__(256) void k_edge(const int* __restrict__ ei,
                                              const float* __restrict__ W1,
                                              const float* __restrict__ b1,
                                              const float* __restrict__ W2,
                                              const float* __restrict__ b2) {
    extern __shared__ float sm[];
    float* W1s = sm;                 // 129*64 = 8256
    float* b1s = W1s + 8256;         // 64
    float* W2s = b1s + 64;           // 64*64 = 4096
    float* b2s = W2s + 4096;         // 64
    float* xs  = b2s + 64;           // 128*132 = 16896
    float* hs  = xs + 16896;         // 128*68 = 8704
    int*   ds  = (int*)(hs + 8704);  // 128

    int tid = threadIdx.x;
    for (int i = tid; i < 8256; i += 256) W1s[i] = W1[i];
    for (int i = tid; i < 4096; i += 256) W2s[i] = W2[i];
    if (tid < 64) { b1s[tid] = b1[tid]; b2s[tid] = b2[tid]; }

    int ebase = blockIdx.x * 128;
    int warp = tid >> 5, lane = tid & 31;
    for (int t = 0; t < 16; t++) {
        int e = warp * 16 + t;
        int ge = ebase + e;
        int s = ei[ge], d = ei[EE + ge];
        if (lane < 16) {
            float4 v = *(const float4*)&g_h[(size_t)s * DD + lane * 4];
            *(float4*)&xs[e * 132 + lane * 4] = v;
        } else {
            float4 v = *(const float4*)&g_h[(size_t)d * DD + (lane - 16) * 4];
            *(float4*)&xs[e * 132 + 64 + (lane - 16) * 4] = v;
        }
        if (lane == 0) { xs[e * 132 + 128] = g_d2[ge]; ds[e] = d; }
    }
    __syncthreads();

    int tr = tid >> 4, tc = tid & 15, c0 = tc * 4;
    float acc[8][4];
#pragma unroll
    for (int i = 0; i < 8; i++) {
        acc[i][0] = b1s[c0];     acc[i][1] = b1s[c0 + 1];
        acc[i][2] = b1s[c0 + 2]; acc[i][3] = b1s[c0 + 3];
    }
    for (int k = 0; k < 129; k++) {
        float4 w = *(const float4*)&W1s[k * DD + c0];
#pragma unroll
        for (int i = 0; i < 8; i++) {
            float xv = xs[(tr + 16 * i) * 132 + k];
            acc[i][0] += xv * w.x; acc[i][1] += xv * w.y;
            acc[i][2] += xv * w.z; acc[i][3] += xv * w.w;
        }
    }
#pragma unroll
    for (int i = 0; i < 8; i++) {
        float4 o;
        o.x = fmaxf(acc[i][0], 0.f); o.y = fmaxf(acc[i][1], 0.f);
        o.z = fmaxf(acc[i][2], 0.f); o.w = fmaxf(acc[i][3], 0.f);
        *(float4*)&hs[(tr + 16 * i) * 68 + c0] = o;
    }
    __syncthreads();

#pragma unroll
    for (int i = 0; i < 8; i++) {
        acc[i][0] = b2s[c0];     acc[i][1] = b2s[c0 + 1];
        acc[i][2] = b2s[c0 + 2]; acc[i][3] = b2s[c0 + 3];
    }
    for (int k = 0; k < 64; k++) {
        float4 w = *(const float4*)&W2s[k * DD + c0];
#pragma unroll
        for (int i = 0; i < 8; i++) {
            float hv = hs[(tr + 16 * i) * 68 + k];
            acc[i][0] += hv * w.x; acc[i][1] += hv * w.y;
            acc[i][2] += hv * w.z; acc[i][3] += hv * w.w;
        }
    }
#pragma unroll
    for (int i = 0; i < 8; i++) {
        int d = ds[tr + 16 * i];
        red_add_v4(&g_agg[(size_t)d * DD + c0], acc[i][0], acc[i][1], acc[i][2], acc[i][3]);
    }
}

// ---- node update: h += relu([h, agg] @ W3 + b3) ----
#define NODE_SMEM (16704 * 4)
__global__ __launch_bounds__(256) void k_node(const float* __restrict__ W3,
                                              const float* __restrict__ b3) {
    extern __shared__ float sm[];
    float* W3s = sm;            // 128*64 = 8192
    float* b3s = W3s + 8192;    // 64
    float* xs  = b3s + 64;      // 64*132 = 8448

    int tid = threadIdx.x;
    for (int i = tid; i < 8192; i += 256) W3s[i] = W3[i];
    if (tid < 64) b3s[tid] = b3[tid];
    int base = blockIdx.x * 64;
    int warp = tid >> 5, lane = tid & 31;
    for (int t = 0; t < 8; t++) {
        int r = warp * 8 + t;
        int g = base + r;
        float4 v = make_float4(0.f, 0.f, 0.f, 0.f);
        if (g < NN) {
            if (lane < 16) v = *(const float4*)&g_h[(size_t)g * DD + lane * 4];
            else           v = *(const float4*)&g_agg[(size_t)g * DD + (lane - 16) * 4];
        }
        if (lane < 16) *(float4*)&xs[r * 132 + lane * 4] = v;
        else           *(float4*)&xs[r * 132 + 64 + (lane - 16) * 4] = v;
    }
    __syncthreads();

    int tr = tid >> 4, tc = tid & 15, c0 = tc * 4;
    float acc[4][4];
#pragma unroll
    for (int i = 0; i < 4; i++) {
        acc[i][0] = b3s[c0];     acc[i][1] = b3s[c0 + 1];
        acc[i][2] = b3s[c0 + 2]; acc[i][3] = b3s[c0 + 3];
    }
    for (int k = 0; k < 128; k++) {
        float4 w = *(const float4*)&W3s[k * DD + c0];
#pragma unroll
        for (int i = 0; i < 4; i++) {
            float xv = xs[(tr + 16 * i) * 132 + k];
            acc[i][0] += xv * w.x; acc[i][1] += xv * w.y;
            acc[i][2] += xv * w.z; acc[i][3] += xv * w.w;
        }
    }
#pragma unroll
    for (int i = 0; i < 4; i++) {
        int r = tr + 16 * i;
        int g = base + r;
        if (g < NN) {
            float4 o;
            o.x = xs[r * 132 + c0 + 0] + fmaxf(acc[i][0], 0.f);
            o.y = xs[r * 132 + c0 + 1] + fmaxf(acc[i][1], 0.f);
            o.z = xs[r * 132 + c0 + 2] + fmaxf(acc[i][2], 0.f);
            o.w = xs[r * 132 + c0 + 3] + fmaxf(acc[i][3], 0.f);
            *(float4*)&g_h[(size_t)g * DD + c0] = o;
        }
    }
}

// ---- final linear + pooled sum: pool[batch] += relu(h) @ Wlin + blin ----
__global__ __launch_bounds__(256) void k_final(const int* __restrict__ batch,
                                               const float* __restrict__ Wl,
                                               const float* __restrict__ bl) {
    __shared__ float Ws[DD * OUTD];
    __shared__ float bs[OUTD];
    __shared__ float xs[64 * 68];
    __shared__ int bb[64];
    int tid = threadIdx.x;
    for (int i = tid; i < DD * OUTD; i += 256) Ws[i] = Wl[i];
    if (tid < OUTD) bs[tid] = bl[tid];
    int base = blockIdx.x * 64;
    int warp = tid >> 5, lane = tid & 31;
    for (int t = 0; t < 8; t++) {
        int r = warp * 8 + t;
        int g = base + r;
        float v0 = 0.f, v1 = 0.f;
        if (g < NN) {
            v0 = fmaxf(g_h[(size_t)g * DD + lane], 0.f);
            v1 = fmaxf(g_h[(size_t)g * DD + lane + 32], 0.f);
            if (lane == 0) bb[r] = batch[g];
        }
        xs[r * 68 + lane] = v0;
        xs[r * 68 + lane + 32] = v1;
    }
    __syncthreads();

    int tr = tid >> 4, tc = tid & 15, c0 = tc * 2;
    float acc[4][2];
#pragma unroll
    for (int i = 0; i < 4; i++) { acc[i][0] = bs[c0]; acc[i][1] = bs[c0 + 1]; }
    for (int k = 0; k < DD; k++) {
        float2 w = *(const float2*)&Ws[k * OUTD + c0];
#pragma unroll
        for (int i = 0; i < 4; i++) {
            float xv = xs[(tr + 16 * i) * 68 + k];
            acc[i][0] += xv * w.x; acc[i][1] += xv * w.y;
        }
    }
#pragma unroll
    for (int i = 0; i < 4; i++) {
        int r = tr + 16 * i;
        int g = base + r;
        if (g < NN) red_add_v2(&g_pool[bb[r] * OUTD + c0], acc[i][0], acc[i][1]);
    }
}

__global__ void k_cnt(const int* __restrict__ batch) {
    int i = blockIdx.x * blockDim.x + threadIdx.x;
    if (i < NN) atomicAdd(&g_cnt[batch[i]], 1.0f);
}

__global__ void k_out(float* __restrict__ out) {
    int i = blockIdx.x * blockDim.x + threadIdx.x;
    if (i < GG * OUTD) out[i] = g_pool[i] / fmaxf(g_cnt[i / OUTD], 1.0f);
}

extern "C" void kernel_launch(void* const* d_in, const int* in_sizes, int n_in,
                              void* d_out, int out_size) {
    const float* pos    = (const float*)d_in[0];
    const int*   z      = (const int*)d_in[1];
    const int*   ei     = (const int*)d_in[2];
    const int*   batch  = (const int*)d_in[3];
    const float* emb    = (const float*)d_in[4];
    const float* t1_Win = (const float*)d_in[5];
    const float* t1_W1  = (const float*)d_in[6];
    const float* t1_b1  = (const float*)d_in[7];
    const float* t1_W2  = (const float*)d_in[8];
    const float* t1_b2  = (const float*)d_in[9];
    const float* t1_W3  = (const float*)d_in[10];
    const float* t1_b3  = (const float*)d_in[11];
    const float* t2_Win = (const float*)d_in[12];
    const float* t2_W1  = (const float*)d_in[13];
    const float* t2_b1  = (const float*)d_in[14];
    const float* t2_W2  = (const float*)d_in[15];
    const float* t2_b2  = (const float*)d_in[16];
    const float* t2_W3  = (const float*)d_in[17];
    const float* t2_b3  = (const float*)d_in[18];
    const float* Wlin   = (const float*)d_in[19];
    const float* blin   = (const float*)d_in[20];
    float* out = (float*)d_out;

    cudaFuncSetAttribute(k_edge, cudaFuncAttributeMaxDynamicSharedMemorySize, EDGE_SMEM);
    cudaFuncSetAttribute(k_node, cudaFuncAttributeMaxDynamicSharedMemorySize, NODE_SMEM);

    const int NT = (NN + 63) / 64;

    k_d2<<<(EE + 255) / 256, 256>>>(pos, ei);
    k_init<<<NT, 256>>>(pos, z, emb, t1_Win);

    for (int t = 0; t < 2; t++) {
        const float* W1 = t ? t2_W1 : t1_W1;
        const float* b1 = t ? t2_b1 : t1_b1;
        const float* W2 = t ? t2_W2 : t1_W2;
        const float* b2 = t ? t2_b2 : t1_b2;
        const float* W3 = t ? t2_W3 : t1_W3;
        const float* b3 = t ? t2_b3 : t1_b3;
        for (int l = 0; l < NLAY; l++) {
            k_zero_agg<<<(NN * DD / 4 + 1023) / 1024, 1024>>>();
            k_edge<<<EE / 128, 256, EDGE_SMEM>>>(ei,
                                                 W1 + l * 129 * DD, b1 + l * DD,
                                                 W2 + l * DD * DD,  b2 + l * DD);
            k_node<<<NT, 256, NODE_SMEM>>>(W3 + l * 128 * DD, b3 + l * DD);
        }
        if (t == 0) k_proj<<<NT, 256>>>(t2_Win);
    }

    k_zero_pool<<<1, 256>>>();
    k_final<<<NT, 256>>>(batch, Wlin, blin);
    k_cnt<<<(NN + 255) / 256, 256>>>(batch);
    k_out<<<(GG * OUTD + 255) / 256, 256>>>(out);
}

// round 4
// speedup vs baseline: 3.7705x; 3.7705x over previous
#include <cuda_runtime.h>
#include <cstddef>

#define NN   100000
#define EE   800000
#define DD   64
#define GG   64
#define OUTD 32
#define FF   61
#define NLAY 4

// ---- device scratch ----
__device__ float g_h[NN * DD];
__device__ float g_agg[NN * DD];   // per-layer "t" accumulator (sum of relu'd edge hiddens)
__device__ float g_p[NN * DD];     // h @ W1a + b1
__device__ float g_q[NN * DD];     // h @ W1b
__device__ float g_d2[EE];
__device__ float g_deg[NN];
__device__ float g_pool[GG * OUTD];
__device__ float g_cnt[GG];

__device__ __forceinline__ void red_add_v4(float* addr, float a, float b, float c, float d) {
    asm volatile("red.global.add.v4.f32 [%0], {%1,%2,%3,%4};"
                 :: "l"(addr), "f"(a), "f"(b), "f"(c), "f"(d) : "memory");
}
__device__ __forceinline__ void red_add_v2(float* addr, float a, float b) {
    asm volatile("red.global.add.v2.f32 [%0], {%1,%2};"
                 :: "l"(addr), "f"(a), "f"(b) : "memory");
}
__device__ __forceinline__ void red_add_f(float* addr, float a) {
    asm volatile("red.global.add.f32 [%0], %1;" :: "l"(addr), "f"(a) : "memory");
}

// ---- one-time prep ----
__global__ void k_d2(const float* __restrict__ pos, const int* __restrict__ ei) {
    int e = blockIdx.x * blockDim.x + threadIdx.x;
    if (e >= EE) return;
    int s = ei[e], d = ei[EE + e];
    float dx = pos[s * 3 + 0] - pos[d * 3 + 0];
    float dy = pos[s * 3 + 1] - pos[d * 3 + 1];
    float dz = pos[s * 3 + 2] - pos[d * 3 + 2];
    g_d2[e] = dx * dx + dy * dy + dz * dz;
}
__global__ void k_zero_deg() {
    int i = blockIdx.x * blockDim.x + threadIdx.x;
    if (i < NN) g_deg[i] = 0.f;
}
__global__ void k_deg(const int* __restrict__ ei) {
    int e = blockIdx.x * blockDim.x + threadIdx.x;
    if (e < EE) red_add_f(&g_deg[ei[EE + e]], 1.0f);
}
__global__ void k_zero_agg() {
    int i = blockIdx.x * blockDim.x + threadIdx.x;
    if (i * 4 < NN * DD) *(float4*)&g_agg[i * 4] = make_float4(0.f, 0.f, 0.f, 0.f);
}
__global__ void k_zero_pool() {
    int i = threadIdx.x;
    for (int j = i; j < GG * OUTD; j += 256) g_pool[j] = 0.f;
    if (i < GG) g_cnt[i] = 0.f;
}

// ---- input embedding + t1 input projection ----
__global__ __launch_bounds__(256) void k_init(const float* __restrict__ pos,
                                              const int* __restrict__ z,
                                              const float* __restrict__ emb,
                                              const float* __restrict__ Win) {
    __shared__ float Ws[DD * DD];
    __shared__ float xs[64 * 68];
    int tid = threadIdx.x;
    for (int i = tid; i < DD * DD; i += 256) Ws[i] = Win[i];
    int base = blockIdx.x * 64;
    int warp = tid >> 5, lane = tid & 31;
    for (int t = 0; t < 8; t++) {
        int r = warp * 8 + t;
        int g = base + r;
        float v0 = 0.f, v1 = 0.f;
        if (g < NN) {
            int zi = z[g];
            v0 = (lane < 3) ? pos[g * 3 + lane] : emb[zi * FF + lane - 3];
            v1 = emb[zi * FF + lane + 29];
        }
        xs[r * 68 + lane] = v0;
        xs[r * 68 + lane + 32] = v1;
    }
    __syncthreads();
    int tr = tid >> 4, tc = tid & 15, c0 = tc * 4;
    float acc[4][4];
#pragma unroll
    for (int i = 0; i < 4; i++)
#pragma unroll
        for (int j = 0; j < 4; j++) acc[i][j] = 0.f;
    for (int k = 0; k < DD; k++) {
        float4 w = *(const float4*)&Ws[k * DD + c0];
#pragma unroll
        for (int i = 0; i < 4; i++) {
            float xv = xs[(tr + 16 * i) * 68 + k];
            acc[i][0] += xv * w.x; acc[i][1] += xv * w.y;
            acc[i][2] += xv * w.z; acc[i][3] += xv * w.w;
        }
    }
#pragma unroll
    for (int i = 0; i < 4; i++) {
        int g = base + tr + 16 * i;
        if (g < NN)
            *(float4*)&g_h[(size_t)g * DD + c0] =
                make_float4(acc[i][0], acc[i][1], acc[i][2], acc[i][3]);
    }
}

// ---- t2 input projection: h = relu(h) @ Win ----
__global__ __launch_bounds__(256) void k_proj(const float* __restrict__ Win) {
    __shared__ float Ws[DD * DD];
    __shared__ float xs[64 * 68];
    int tid = threadIdx.x;
    for (int i = tid; i < DD * DD; i += 256) Ws[i] = Win[i];
    int base = blockIdx.x * 64;
    int warp = tid >> 5, lane = tid & 31;
    for (int t = 0; t < 8; t++) {
        int r = warp * 8 + t;
        int g = base + r;
        float v0 = 0.f, v1 = 0.f;
        if (g < NN) {
            v0 = fmaxf(g_h[(size_t)g * DD + lane], 0.f);
            v1 = fmaxf(g_h[(size_t)g * DD + lane + 32], 0.f);
        }
        xs[r * 68 + lane] = v0;
        xs[r * 68 + lane + 32] = v1;
    }
    __syncthreads();
    int tr = tid >> 4, tc = tid & 15, c0 = tc * 4;
    float acc[4][4];
#pragma unroll
    for (int i = 0; i < 4; i++)
#pragma unroll
        for (int j = 0; j < 4; j++) acc[i][j] = 0.f;
    for (int k = 0; k < DD; k++) {
        float4 w = *(const float4*)&Ws[k * DD + c0];
#pragma unroll
        for (int i = 0; i < 4; i++) {
            float xv = xs[(tr + 16 * i) * 68 + k];
            acc[i][0] += xv * w.x; acc[i][1] += xv * w.y;
            acc[i][2] += xv * w.z; acc[i][3] += xv * w.w;
        }
    }
#pragma unroll
    for (int i = 0; i < 4; i++) {
        int g = base + tr + 16 * i;
        if (g < NN)
            *(float4*)&g_h[(size_t)g * DD + c0] =
                make_float4(acc[i][0], acc[i][1], acc[i][2], acc[i][3]);
    }
}

// ---- per-layer: p = h@W1a + b1, q = h@W1b  (128-node tiles) ----
#define PQ_SMEM ((8192 + 64 + 128 * 68) * 4)
__global__ __launch_bounds__(256) void k_pq(const float* __restrict__ W1,
                                            const float* __restrict__ b1) {
    extern __shared__ float sm[];
    float* Ws  = sm;          // W1 rows 0..127 (W1a then W1b), 8192 floats
    float* b1s = Ws + 8192;   // 64
    float* xs  = b1s + 64;    // 128*68
    int tid = threadIdx.x;
    for (int i = tid; i < 8192; i += 256) Ws[i] = W1[i];
    if (tid < 64) b1s[tid] = b1[tid];

    int base = blockIdx.x * 128;
    for (int idx = tid; idx < 128 * 16; idx += 256) {
        int r = idx >> 4, cq = idx & 15;
        int g = base + r;
        float4 v = make_float4(0.f, 0.f, 0.f, 0.f);
        if (g < NN) v = *(const float4*)&g_h[(size_t)g * DD + cq * 4];
        *(float4*)&xs[r * 68 + cq * 4] = v;
    }
    __syncthreads();

    int tr = tid >> 4, tc = tid & 15, c0 = tc * 4;
    float ap[8][4], aq[8][4];
#pragma unroll
    for (int i = 0; i < 8; i++) {
        ap[i][0] = b1s[c0];     ap[i][1] = b1s[c0 + 1];
        ap[i][2] = b1s[c0 + 2]; ap[i][3] = b1s[c0 + 3];
        aq[i][0] = aq[i][1] = aq[i][2] = aq[i][3] = 0.f;
    }
#pragma unroll 4
    for (int k = 0; k < DD; k++) {
        float4 wa = *(const float4*)&Ws[k * DD + c0];
        float4 wb = *(const float4*)&Ws[(64 + k) * DD + c0];
#pragma unroll
        for (int i = 0; i < 8; i++) {
            float xv = xs[(tr + 16 * i) * 68 + k];
            ap[i][0] += xv * wa.x; ap[i][1] += xv * wa.y;
            ap[i][2] += xv * wa.z; ap[i][3] += xv * wa.w;
            aq[i][0] += xv * wb.x; aq[i][1] += xv * wb.y;
            aq[i][2] += xv * wb.z; aq[i][3] += xv * wb.w;
        }
    }
#pragma unroll
    for (int i = 0; i < 8; i++) {
        int g = base + tr + 16 * i;
        if (g < NN) {
            *(float4*)&g_p[(size_t)g * DD + c0] = make_float4(ap[i][0], ap[i][1], ap[i][2], ap[i][3]);
            *(float4*)&g_q[(size_t)g * DD + c0] = make_float4(aq[i][0], aq[i][1], aq[i][2], aq[i][3]);
        }
    }
}

// ---- per-layer edge pass: t[dst] += relu(p[src] + q[dst] + d2*w1c) ----
// 16 threads per edge (one float4 chunk each), 128 edges per block.
__global__ __launch_bounds__(256) void k_edge2(const int* __restrict__ ei,
                                               const float* __restrict__ w1c) {
    __shared__ float wc[64];
    int tid = threadIdx.x;
    if (tid < 64) wc[tid] = w1c[tid];
    __syncthreads();
    int grp = tid >> 4, sub = tid & 15;
    int base = blockIdx.x * 128;
    float4 wv = *(const float4*)&wc[sub * 4];
#pragma unroll 2
    for (int it = 0; it < 8; it++) {
        int ge = base + it * 16 + grp;
        int s = ei[ge], d = ei[EE + ge];
        float d2 = g_d2[ge];
        float4 pv = *(const float4*)&g_p[(size_t)s * DD + sub * 4];
        float4 qv = *(const float4*)&g_q[(size_t)d * DD + sub * 4];
        float rx = fmaxf(fmaf(d2, wv.x, pv.x + qv.x), 0.f);
        float ry = fmaxf(fmaf(d2, wv.y, pv.y + qv.y), 0.f);
        float rz = fmaxf(fmaf(d2, wv.z, pv.z + qv.z), 0.f);
        float rw = fmaxf(fmaf(d2, wv.w, pv.w + qv.w), 0.f);
        red_add_v4(&g_agg[(size_t)d * DD + sub * 4], rx, ry, rz, rw);
    }
}

// ---- per-layer node pass: agg = t@W2 + deg*b2; h += relu([h,agg]@W3 + b3) ----
#define NODE_SMEM ((4096 + 8192 + 64 + 64 + 64 + 64 * 68 + 64 * 132) * 4)
__global__ __launch_bounds__(256) void k_node2(const float* __restrict__ W2,
                                               const float* __restrict__ b2,
                                               const float* __restrict__ W3,
                                               const float* __restrict__ b3) {
    extern __shared__ float sm[];
    float* W2s  = sm;             // 4096
    float* W3s  = W2s + 4096;     // 8192
    float* b2s  = W3s + 8192;     // 64
    float* b3s  = b2s + 64;       // 64
    float* degs = b3s + 64;       // 64
    float* ts   = degs + 64;      // 64*68
    float* xa   = ts + 64 * 68;   // 64*132  (h in cols 0..63, agg in 64..127)

    int tid = threadIdx.x;
    for (int i = tid; i < 4096; i += 256) W2s[i] = W2[i];
    for (int i = tid; i < 8192; i += 256) W3s[i] = W3[i];
    if (tid < 64) { b2s[tid] = b2[tid]; b3s[tid] = b3[tid]; }

    int base = blockIdx.x * 64;
    if (tid < 64) {
        int g = base + tid;
        degs[tid] = (g < NN) ? g_deg[g] : 0.f;
    }
    for (int idx = tid; idx < 64 * 16; idx += 256) {
        int r = idx >> 4, cq = idx & 15;
        int g = base + r;
        float4 hv = make_float4(0.f, 0.f, 0.f, 0.f);
        float4 tv = make_float4(0.f, 0.f, 0.f, 0.f);
        if (g < NN) {
            hv = *(const float4*)&g_h[(size_t)g * DD + cq * 4];
            tv = *(const float4*)&g_agg[(size_t)g * DD + cq * 4];
        }
        *(float4*)&xa[r * 132 + cq * 4] = hv;
        *(float4*)&ts[r * 68 + cq * 4] = tv;
    }
    __syncthreads();

    int tr = tid >> 4, tc = tid & 15, c0 = tc * 4;
    float acc[4][4];
    // GEMM1: agg = t @ W2 + deg*b2 -> xa cols 64..127
#pragma unroll
    for (int i = 0; i < 4; i++) acc[i][0] = acc[i][1] = acc[i][2] = acc[i][3] = 0.f;
#pragma unroll 4
    for (int k = 0; k < DD; k++) {
        float4 w = *(const float4*)&W2s[k * DD + c0];
#pragma unroll
        for (int i = 0; i < 4; i++) {
            float xv = ts[(tr + 16 * i) * 68 + k];
            acc[i][0] += xv * w.x; acc[i][1] += xv * w.y;
            acc[i][2] += xv * w.z; acc[i][3] += xv * w.w;
        }
    }
#pragma unroll
    for (int i = 0; i < 4; i++) {
        int r = tr + 16 * i;
        float dg = degs[r];
        xa[r * 132 + 64 + c0 + 0] = acc[i][0] + dg * b2s[c0 + 0];
        xa[r * 132 + 64 + c0 + 1] = acc[i][1] + dg * b2s[c0 + 1];
        xa[r * 132 + 64 + c0 + 2] = acc[i][2] + dg * b2s[c0 + 2];
        xa[r * 132 + 64 + c0 + 3] = acc[i][3] + dg * b2s[c0 + 3];
    }
    __syncthreads();

    // GEMM2: h += relu([h,agg] @ W3 + b3)
#pragma unroll
    for (int i = 0; i < 4; i++) {
        acc[i][0] = b3s[c0];     acc[i][1] = b3s[c0 + 1];
        acc[i][2] = b3s[c0 + 2]; acc[i][3] = b3s[c0 + 3];
    }
#pragma unroll 4
    for (int k = 0; k < 128; k++) {
        float4 w = *(const float4*)&W3s[k * DD + c0];
#pragma unroll
        for (int i = 0; i < 4; i++) {
            float xv = xa[(tr + 16 * i) * 132 + k];
            acc[i][0] += xv * w.x; acc[i][1] += xv * w.y;
            acc[i][2] += xv * w.z; acc[i][3] += xv * w.w;
        }
    }
#pragma unroll
    for (int i = 0; i < 4; i++) {
        int r = tr + 16 * i;
        int g = base + r;
        if (g < NN) {
            float4 o;
            o.x = xa[r * 132 + c0 + 0] + fmaxf(acc[i][0], 0.f);
            o.y = xa[r * 132 + c0 + 1] + fmaxf(acc[i][1], 0.f);
            o.z = xa[r * 132 + c0 + 2] + fmaxf(acc[i][2], 0.f);
            o.w = xa[r * 132 + c0 + 3] + fmaxf(acc[i][3], 0.f);
            *(float4*)&g_h[(size_t)g * DD + c0] = o;
        }
    }
}

// ---- final linear + pool ----
__global__ __launch_bounds__(256) void k_final(const int* __restrict__ batch,
                                               const float* __restrict__ Wl,
                                               const float* __restrict__ bl) {
    __shared__ float Ws[DD * OUTD];
    __shared__ float bs[OUTD];
    __shared__ float xs[64 * 68];
    __shared__ int bb[64];
    int tid = threadIdx.x;
    for (int i = tid; i < DD * OUTD; i += 256) Ws[i] = Wl[i];
    if (tid < OUTD) bs[tid] = bl[tid];
    int base = blockIdx.x * 64;
    int warp = tid >> 5, lane = tid & 31;
    for (int t = 0; t < 8; t++) {
        int r = warp * 8 + t;
        int g = base + r;
        float v0 = 0.f, v1 = 0.f;
        if (g < NN) {
            v0 = fmaxf(g_h[(size_t)g * DD + lane], 0.f);
            v1 = fmaxf(g_h[(size_t)g * DD + lane + 32], 0.f);
            if (lane == 0) bb[r] = batch[g];
        }
        xs[r * 68 + lane] = v0;
        xs[r * 68 + lane + 32] = v1;
    }
    __syncthreads();

    int tr = tid >> 4, tc = tid & 15, c0 = tc * 2;
    float acc[4][2];
#pragma unroll
    for (int i = 0; i < 4; i++) { acc[i][0] = bs[c0]; acc[i][1] = bs[c0 + 1]; }
    for (int k = 0; k < DD; k++) {
        float2 w = *(const float2*)&Ws[k * OUTD + c0];
#pragma unroll
        for (int i = 0; i < 4; i++) {
            float xv = xs[(tr + 16 * i) * 68 + k];
            acc[i][0] += xv * w.x; acc[i][1] += xv * w.y;
        }
    }
#pragma unroll
    for (int i = 0; i < 4; i++) {
        int r = tr + 16 * i;
        int g = base + r;
        if (g < NN) red_add_v2(&g_pool[bb[r] * OUTD + c0], acc[i][0], acc[i][1]);
    }
}

__global__ void k_cnt(const int* __restrict__ batch) {
    int i = blockIdx.x * blockDim.x + threadIdx.x;
    if (i < NN) red_add_f(&g_cnt[batch[i]], 1.0f);
}
__global__ void k_out(float* __restrict__ out) {
    int i = blockIdx.x * blockDim.x + threadIdx.x;
    if (i < GG * OUTD) out[i] = g_pool[i] / fmaxf(g_cnt[i / OUTD], 1.0f);
}

extern "C" void kernel_launch(void* const* d_in, const int* in_sizes, int n_in,
                              void* d_out, int out_size) {
    const float* pos    = (const float*)d_in[0];
    const int*   z      = (const int*)d_in[1];
    const int*   ei     = (const int*)d_in[2];
    const int*   batch  = (const int*)d_in[3];
    const float* emb    = (const float*)d_in[4];
    const float* t1_Win = (const float*)d_in[5];
    const float* t1_W1  = (const float*)d_in[6];
    const float* t1_b1  = (const float*)d_in[7];
    const float* t1_W2  = (const float*)d_in[8];
    const float* t1_b2  = (const float*)d_in[9];
    const float* t1_W3  = (const float*)d_in[10];
    const float* t1_b3  = (const float*)d_in[11];
    const float* t2_Win = (const float*)d_in[12];
    const float* t2_W1  = (const float*)d_in[13];
    const float* t2_b1  = (const float*)d_in[14];
    const float* t2_W2  = (const float*)d_in[15];
    const float* t2_b2  = (const float*)d_in[16];
    const float* t2_W3  = (const float*)d_in[17];
    const float* t2_b3  = (const float*)d_in[18];
    const float* Wlin   = (const float*)d_in[19];
    const float* blin   = (const float*)d_in[20];
    float* out = (float*)d_out;

    cudaFuncSetAttribute(k_pq,    cudaFuncAttributeMaxDynamicSharedMemorySize, PQ_SMEM);
    cudaFuncSetAttribute(k_node2, cudaFuncAttributeMaxDynamicSharedMemorySize, NODE_SMEM);

    const int NT64  = (NN + 63) / 64;
    const int NT128 = (NN + 127) / 128;

    k_d2<<<(EE + 255) / 256, 256>>>(pos, ei);
    k_zero_deg<<<(NN + 255) / 256, 256>>>();
    k_deg<<<(EE + 255) / 256, 256>>>(ei);
    k_init<<<NT64, 256>>>(pos, z, emb, t1_Win);

    for (int t = 0; t < 2; t++) {
        const float* W1 = t ? t2_W1 : t1_W1;
        const float* b1 = t ? t2_b1 : t1_b1;
        const float* W2 = t ? t2_W2 : t1_W2;
        const float* b2 = t ? t2_b2 : t1_b2;
        const float* W3 = t ? t2_W3 : t1_W3;
        const float* b3 = t ? t2_b3 : t1_b3;
        for (int l = 0; l < NLAY; l++) {
            const float* W1l = W1 + l * 129 * DD;
            k_zero_agg<<<(NN * DD / 4 + 1023) / 1024, 1024>>>();
            k_pq<<<NT128, 256, PQ_SMEM>>>(W1l, b1 + l * DD);
            k_edge2<<<EE / 128, 256>>>(ei, W1l + 128 * DD);
            k_node2<<<NT64, 256, NODE_SMEM>>>(W2 + l * DD * DD, b2 + l * DD,
                                              W3 + l * 128 * DD, b3 + l * DD);
        }
        if (t == 0) k_proj<<<NT64, 256>>>(t2_Win);
    }

    k_zero_pool<<<1, 256>>>();
    k_final<<<NT64, 256>>>(batch, Wlin, blin);
    k_cnt<<<(NN + 255) / 256, 256>>>(batch);
    k_out<<<(GG * OUTD + 255) / 256, 256>>>(out);
}

// round 5
// speedup vs baseline: 4.3204x; 1.1458x over previous
#include <cuda_runtime.h>
#include <cstddef>

#define NN   100000
#define EE   800000
#define DD   64
#define GG   64
#define OUTD 32
#define FF   61
#define NLAY 4

#define SCAN_B  1024
#define SCAN_NB ((NN + SCAN_B - 1) / SCAN_B)

// ---- device scratch ----
__device__ float g_h[NN * DD];
__device__ float g_p[NN * DD];     // h @ W1a + b1
__device__ float g_q[NN * DD];     // h @ W1b
__device__ int   g_deg_i[NN];
__device__ int   g_cur[NN];
__device__ int   g_roff[NN + 1];   // CSR row offsets (dst-sorted)
__device__ int   g_bsum[SCAN_NB];
__device__ int   g_boff[SCAN_NB];
__device__ int   g_esrc[EE];       // src per sorted edge
__device__ float g_ed2[EE];        // d2 per sorted edge
__device__ float g_pool[GG * OUTD];
__device__ float g_cnt[GG];

__device__ __forceinline__ void red_add_v2(float* addr, float a, float b) {
    asm volatile("red.global.add.v2.f32 [%0], {%1,%2};"
                 :: "l"(addr), "f"(a), "f"(b) : "memory");
}
__device__ __forceinline__ void red_add_f(float* addr, float a) {
    asm volatile("red.global.add.f32 [%0], %1;" :: "l"(addr), "f"(a) : "memory");
}

// ---- packed f32x2 helpers ----
__device__ __forceinline__ unsigned long long pk(float x, float y) {
    unsigned long long r;
    asm("mov.b64 %0, {%1,%2};" : "=l"(r)
        : "r"(__float_as_uint(x)), "r"(__float_as_uint(y)));
    return r;
}
__device__ __forceinline__ float2 unpk(unsigned long long v) {
    unsigned int lo, hi;
    asm("mov.b64 {%0,%1}, %2;" : "=r"(lo), "=r"(hi) : "l"(v));
    return make_float2(__uint_as_float(lo), __uint_as_float(hi));
}
__device__ __forceinline__ void ffma2(unsigned long long& acc,
                                      unsigned long long a, unsigned long long b) {
    asm("fma.rn.f32x2 %0, %1, %2, %0;" : "+l"(acc) : "l"(a), "l"(b));
}

// ================= CSR build =================
__global__ void k_hist_zero() {
    int i = blockIdx.x * blockDim.x + threadIdx.x;
    if (i < NN) { g_deg_i[i] = 0; g_cur[i] = 0; }
}
__global__ void k_hist(const int* __restrict__ ei) {
    int e = blockIdx.x * blockDim.x + threadIdx.x;
    if (e < EE) atomicAdd(&g_deg_i[ei[EE + e]], 1);
}
__global__ __launch_bounds__(SCAN_B) void k_scan1() {
    __shared__ int s[SCAN_B];
    int i = blockIdx.x * SCAN_B + threadIdx.x;
    int v = (i < NN) ? g_deg_i[i] : 0;
    s[threadIdx.x] = v;
    __syncthreads();
    for (int off = 1; off < SCAN_B; off <<= 1) {
        int t = (threadIdx.x >= off) ? s[threadIdx.x - off] : 0;
        __syncthreads();
        s[threadIdx.x] += t;
        __syncthreads();
    }
    if (i < NN) g_roff[i] = s[threadIdx.x] - v;
    if (threadIdx.x == SCAN_B - 1) g_bsum[blockIdx.x] = s[threadIdx.x];
}
__global__ __launch_bounds__(128) void k_scan2() {
    __shared__ int s[128];
    int t = threadIdx.x;
    int v = (t < SCAN_NB) ? g_bsum[t] : 0;
    s[t] = v;
    __syncthreads();
    for (int off = 1; off < 128; off <<= 1) {
        int u = (t >= off) ? s[t - off] : 0;
        __syncthreads();
        s[t] += u;
        __syncthreads();
    }
    if (t < SCAN_NB) g_boff[t] = s[t] - v;
    if (t == 127) g_roff[NN] = s[127];
}
__global__ __launch_bounds__(SCAN_B) void k_scan3() {
    int i = blockIdx.x * SCAN_B + threadIdx.x;
    if (i < NN) g_roff[i] += g_boff[blockIdx.x];
}
__global__ void k_scatter(const float* __restrict__ pos, const int* __restrict__ ei) {
    int e = blockIdx.x * blockDim.x + threadIdx.x;
    if (e >= EE) return;
    int s = ei[e], d = ei[EE + e];
    float dx = pos[s * 3 + 0] - pos[d * 3 + 0];
    float dy = pos[s * 3 + 1] - pos[d * 3 + 1];
    float dz = pos[s * 3 + 2] - pos[d * 3 + 2];
    float d2 = dx * dx + dy * dy + dz * dz;
    int p = g_roff[d] + atomicAdd(&g_cur[d], 1);
    g_esrc[p] = s;
    g_ed2[p] = d2;
}

// ================= input / projection =================
__global__ __launch_bounds__(256) void k_init(const float* __restrict__ pos,
                                              const int* __restrict__ z,
                                              const float* __restrict__ emb,
                                              const float* __restrict__ Win) {
    __shared__ float Ws[DD * DD];
    __shared__ float xs[64 * 68];
    int tid = threadIdx.x;
    for (int i = tid; i < DD * DD; i += 256) Ws[i] = Win[i];
    int base = blockIdx.x * 64;
    int warp = tid >> 5, lane = tid & 31;
    for (int t = 0; t < 8; t++) {
        int r = warp * 8 + t;
        int g = base + r;
        float v0 = 0.f, v1 = 0.f;
        if (g < NN) {
            int zi = z[g];
            v0 = (lane < 3) ? pos[g * 3 + lane] : emb[zi * FF + lane - 3];
            v1 = emb[zi * FF + lane + 29];
        }
        xs[r * 68 + lane] = v0;
        xs[r * 68 + lane + 32] = v1;
    }
    __syncthreads();
    int tr = tid >> 4, tc = tid & 15, c0 = tc * 4;
    float acc[4][4];
#pragma unroll
    for (int i = 0; i < 4; i++)
#pragma unroll
        for (int j = 0; j < 4; j++) acc[i][j] = 0.f;
    for (int k = 0; k < DD; k++) {
        float4 w = *(const float4*)&Ws[k * DD + c0];
#pragma unroll
        for (int i = 0; i < 4; i++) {
            float xv = xs[(tr + 16 * i) * 68 + k];
            acc[i][0] += xv * w.x; acc[i][1] += xv * w.y;
            acc[i][2] += xv * w.z; acc[i][3] += xv * w.w;
        }
    }
#pragma unroll
    for (int i = 0; i < 4; i++) {
        int g = base + tr + 16 * i;
        if (g < NN)
            *(float4*)&g_h[(size_t)g * DD + c0] =
                make_float4(acc[i][0], acc[i][1], acc[i][2], acc[i][3]);
    }
}

__global__ __launch_bounds__(256) void k_proj(const float* __restrict__ Win) {
    __shared__ float Ws[DD * DD];
    __shared__ float xs[64 * 68];
    int tid = threadIdx.x;
    for (int i = tid; i < DD * DD; i += 256) Ws[i] = Win[i];
    int base = blockIdx.x * 64;
    int warp = tid >> 5, lane = tid & 31;
    for (int t = 0; t < 8; t++) {
        int r = warp * 8 + t;
        int g = base + r;
        float v0 = 0.f, v1 = 0.f;
        if (g < NN) {
            v0 = fmaxf(g_h[(size_t)g * DD + lane], 0.f);
            v1 = fmaxf(g_h[(size_t)g * DD + lane + 32], 0.f);
        }
        xs[r * 68 + lane] = v0;
        xs[r * 68 + lane + 32] = v1;
    }
    __syncthreads();
    int tr = tid >> 4, tc = tid & 15, c0 = tc * 4;
    float acc[4][4];
#pragma unroll
    for (int i = 0; i < 4; i++)
#pragma unroll
        for (int j = 0; j < 4; j++) acc[i][j] = 0.f;
    for (int k = 0; k < DD; k++) {
        float4 w = *(const float4*)&Ws[k * DD + c0];
#pragma unroll
        for (int i = 0; i < 4; i++) {
            float xv = xs[(tr + 16 * i) * 68 + k];
            acc[i][0] += xv * w.x; acc[i][1] += xv * w.y;
            acc[i][2] += xv * w.z; acc[i][3] += xv * w.w;
        }
    }
#pragma unroll
    for (int i = 0; i < 4; i++) {
        int g = base + tr + 16 * i;
        if (g < NN)
            *(float4*)&g_h[(size_t)g * DD + c0] =
                make_float4(acc[i][0], acc[i][1], acc[i][2], acc[i][3]);
    }
}

// ================= per-layer: p = h@W1a + b1, q = h@W1b =================
#define PQ_SMEM ((8192 + 64 + 128 * 68) * 4)
__global__ __launch_bounds__(256) void k_pq(const float* __restrict__ W1,
                                            const float* __restrict__ b1) {
    extern __shared__ float sm[];
    float* Ws  = sm;          // 8192: W1a rows 0..63, W1b rows 64..127
    float* b1s = Ws + 8192;
    float* xs  = b1s + 64;    // 128*68
    int tid = threadIdx.x;
    for (int i = tid; i < 8192; i += 256) Ws[i] = W1[i];
    if (tid < 64) b1s[tid] = b1[tid];

    int base = blockIdx.x * 128;
    for (int idx = tid; idx < 128 * 16; idx += 256) {
        int r = idx >> 4, cq = idx & 15;
        int g = base + r;
        float4 v = make_float4(0.f, 0.f, 0.f, 0.f);
        if (g < NN) v = *(const float4*)&g_h[(size_t)g * DD + cq * 4];
        *(float4*)&xs[r * 68 + cq * 4] = v;
    }
    __syncthreads();

    int tr = tid >> 4, tc = tid & 15, c0 = tc * 4;
    unsigned long long ap[8][2], aq[8][2];
    unsigned long long bp0 = pk(b1s[c0], b1s[c0 + 1]);
    unsigned long long bp1 = pk(b1s[c0 + 2], b1s[c0 + 3]);
#pragma unroll
    for (int i = 0; i < 8; i++) {
        ap[i][0] = bp0; ap[i][1] = bp1;
        aq[i][0] = pk(0.f, 0.f); aq[i][1] = aq[i][0];
    }
#pragma unroll 4
    for (int k = 0; k < DD; k++) {
        ulonglong2 wa = *(const ulonglong2*)&Ws[k * DD + c0];
        ulonglong2 wb = *(const ulonglong2*)&Ws[(64 + k) * DD + c0];
#pragma unroll
        for (int i = 0; i < 8; i++) {
            float xv = xs[(tr + 16 * i) * 68 + k];
            unsigned long long xx = pk(xv, xv);
            ffma2(ap[i][0], xx, wa.x); ffma2(ap[i][1], xx, wa.y);
            ffma2(aq[i][0], xx, wb.x); ffma2(aq[i][1], xx, wb.y);
        }
    }
#pragma unroll
    for (int i = 0; i < 8; i++) {
        int g = base + tr + 16 * i;
        if (g < NN) {
            float2 a0 = unpk(ap[i][0]), a1 = unpk(ap[i][1]);
            float2 q0 = unpk(aq[i][0]), q1 = unpk(aq[i][1]);
            *(float4*)&g_p[(size_t)g * DD + c0] = make_float4(a0.x, a0.y, a1.x, a1.y);
            *(float4*)&g_q[(size_t)g * DD + c0] = make_float4(q0.x, q0.y, q1.x, q1.y);
        }
    }
}

// ================= per-layer fused edge-gather + node update =================
// t[node] = sum_{e in CSR[node]} relu(p[src] + q[node] + d2*w1c)
// agg = t @ W2 + deg*b2 ; h += relu([h, agg] @ W3 + b3)
#define LAYER_SMEM ((4096 + 8192 + 64 + 64 + 64 + 64 + 64 * 68 + 64 * 132) * 4)
__global__ __launch_bounds__(256) void k_layer(const float* __restrict__ W2,
                                               const float* __restrict__ b2,
                                               const float* __restrict__ W3,
                                               const float* __restrict__ b3,
                                               const float* __restrict__ w1c) {
    extern __shared__ float sm[];
    float* W2s  = sm;              // 4096
    float* W3s  = W2s + 4096;      // 8192
    float* b2s  = W3s + 8192;      // 64
    float* b3s  = b2s + 64;        // 64
    float* wcs  = b3s + 64;        // 64
    float* degs = wcs + 64;        // 64
    float* ts   = degs + 64;       // 64*68
    float* xa   = ts + 64 * 68;    // 64*132 (h cols 0..63, agg cols 64..127)

    int tid = threadIdx.x;
    for (int i = tid; i < 4096; i += 256) W2s[i] = W2[i];
    for (int i = tid; i < 8192; i += 256) W3s[i] = W3[i];
    if (tid < 64) { b2s[tid] = b2[tid]; b3s[tid] = b3[tid]; wcs[tid] = w1c[tid]; }

    int base = blockIdx.x * 64;
    // load h rows into xa cols 0..63
    for (int idx = tid; idx < 64 * 16; idx += 256) {
        int r = idx >> 4, cq = idx & 15;
        int g = base + r;
        float4 hv = make_float4(0.f, 0.f, 0.f, 0.f);
        if (g < NN) hv = *(const float4*)&g_h[(size_t)g * DD + cq * 4];
        *(float4*)&xa[r * 132 + cq * 4] = hv;
    }
    __syncthreads();   // wcs ready for phase A

    // ---- phase A: CSR gather, 4 threads per node, 16 floats each ----
    {
        int grp = tid >> 2, sub = tid & 3;
        int node = base + grp;
        int cb = sub * 16;
        float ta[16];
#pragma unroll
        for (int j = 0; j < 16; j++) ta[j] = 0.f;
        if (sub == 0) degs[grp] = 0.f;
        if (node < NN) {
            float4 q0 = *(const float4*)&g_q[(size_t)node * DD + cb + 0];
            float4 q1 = *(const float4*)&g_q[(size_t)node * DD + cb + 4];
            float4 q2 = *(const float4*)&g_q[(size_t)node * DD + cb + 8];
            float4 q3 = *(const float4*)&g_q[(size_t)node * DD + cb + 12];
            float4 w0 = *(const float4*)&wcs[cb + 0];
            float4 w1 = *(const float4*)&wcs[cb + 4];
            float4 w2 = *(const float4*)&wcs[cb + 8];
            float4 w3 = *(const float4*)&wcs[cb + 12];
            int r0 = g_roff[node], r1 = g_roff[node + 1];
            if (sub == 0) degs[grp] = (float)(r1 - r0);
            for (int r = r0; r < r1; r++) {
                int s = g_esrc[r];
                float d2 = g_ed2[r];
                const float* pp = &g_p[(size_t)s * DD + cb];
                float4 p0 = *(const float4*)(pp + 0);
                float4 p1 = *(const float4*)(pp + 4);
                float4 p2 = *(const float4*)(pp + 8);
                float4 p3 = *(const float4*)(pp + 12);
                ta[0]  += fmaxf(fmaf(d2, w0.x, p0.x + q0.x), 0.f);
                ta[1]  += fmaxf(fmaf(d2, w0.y, p0.y + q0.y), 0.f);
                ta[2]  += fmaxf(fmaf(d2, w0.z, p0.z + q0.z), 0.f);
                ta[3]  += fmaxf(fmaf(d2, w0.w, p0.w + q0.w), 0.f);
                ta[4]  += fmaxf(fmaf(d2, w1.x, p1.x + q1.x), 0.f);
                ta[5]  += fmaxf(fmaf(d2, w1.y, p1.y + q1.y), 0.f);
                ta[6]  += fmaxf(fmaf(d2, w1.z, p1.z + q1.z), 0.f);
                ta[7]  += fmaxf(fmaf(d2, w1.w, p1.w + q1.w), 0.f);
                ta[8]  += fmaxf(fmaf(d2, w2.x, p2.x + q2.x), 0.f);
                ta[9]  += fmaxf(fmaf(d2, w2.y, p2.y + q2.y), 0.f);
                ta[10] += fmaxf(fmaf(d2, w2.z, p2.z + q2.z), 0.f);
                ta[11] += fmaxf(fmaf(d2, w2.w, p2.w + q2.w), 0.f);
                ta[12] += fmaxf(fmaf(d2, w3.x, p3.x + q3.x), 0.f);
                ta[13] += fmaxf(fmaf(d2, w3.y, p3.y + q3.y), 0.f);
                ta[14] += fmaxf(fmaf(d2, w3.z, p3.z + q3.z), 0.f);
                ta[15] += fmaxf(fmaf(d2, w3.w, p3.w + q3.w), 0.f);
            }
        }
        *(float4*)&ts[grp * 68 + cb + 0]  = make_float4(ta[0], ta[1], ta[2], ta[3]);
        *(float4*)&ts[grp * 68 + cb + 4]  = make_float4(ta[4], ta[5], ta[6], ta[7]);
        *(float4*)&ts[grp * 68 + cb + 8]  = make_float4(ta[8], ta[9], ta[10], ta[11]);
        *(float4*)&ts[grp * 68 + cb + 12] = make_float4(ta[12], ta[13], ta[14], ta[15]);
    }
    __syncthreads();

    int tr = tid >> 4, tc = tid & 15, c0 = tc * 4;
    // ---- GEMM1: agg = t @ W2 + deg*b2 -> xa cols 64..127 ----
    {
        unsigned long long acc[4][2];
        unsigned long long z = pk(0.f, 0.f);
#pragma unroll
        for (int i = 0; i < 4; i++) { acc[i][0] = z; acc[i][1] = z; }
#pragma unroll 4
        for (int k = 0; k < DD; k++) {
            ulonglong2 w = *(const ulonglong2*)&W2s[k * DD + c0];
#pragma unroll
            for (int i = 0; i < 4; i++) {
                float xv = ts[(tr + 16 * i) * 68 + k];
                unsigned long long xx = pk(xv, xv);
                ffma2(acc[i][0], xx, w.x); ffma2(acc[i][1], xx, w.y);
            }
        }
#pragma unroll
        for (int i = 0; i < 4; i++) {
            int r = tr + 16 * i;
            float dg = degs[r];
            float2 a0 = unpk(acc[i][0]), a1 = unpk(acc[i][1]);
            xa[r * 132 + 64 + c0 + 0] = fmaf(dg, b2s[c0 + 0], a0.x);
            xa[r * 132 + 64 + c0 + 1] = fmaf(dg, b2s[c0 + 1], a0.y);
            xa[r * 132 + 64 + c0 + 2] = fmaf(dg, b2s[c0 + 2], a1.x);
            xa[r * 132 + 64 + c0 + 3] = fmaf(dg, b2s[c0 + 3], a1.y);
        }
    }
    __syncthreads();

    // ---- GEMM2: h += relu([h,agg] @ W3 + b3) ----
    {
        unsigned long long acc[4][2];
        unsigned long long bp0 = pk(b3s[c0], b3s[c0 + 1]);
        unsigned long long bp1 = pk(b3s[c0 + 2], b3s[c0 + 3]);
#pragma unroll
        for (int i = 0; i < 4; i++) { acc[i][0] = bp0; acc[i][1] = bp1; }
#pragma unroll 4
        for (int k = 0; k < 128; k++) {
            ulonglong2 w = *(const ulonglong2*)&W3s[k * DD + c0];
#pragma unroll
            for (int i = 0; i < 4; i++) {
                float xv = xa[(tr + 16 * i) * 132 + k];
                unsigned long long xx = pk(xv, xv);
                ffma2(acc[i][0], xx, w.x); ffma2(acc[i][1], xx, w.y);
            }
        }
#pragma unroll
        for (int i = 0; i < 4; i++) {
            int r = tr + 16 * i;
            int g = base + r;
            if (g < NN) {
                float2 a0 = unpk(acc[i][0]), a1 = unpk(acc[i][1]);
                float4 o;
                o.x = xa[r * 132 + c0 + 0] + fmaxf(a0.x, 0.f);
                o.y = xa[r * 132 + c0 + 1] + fmaxf(a0.y, 0.f);
                o.z = xa[r * 132 + c0 + 2] + fmaxf(a1.x, 0.f);
                o.w = xa[r * 132 + c0 + 3] + fmaxf(a1.y, 0.f);
                *(float4*)&g_h[(size_t)g * DD + c0] = o;
            }
        }
    }
}

// ================= final linear + pool =================
__global__ void k_zero_pool() {
    int i = threadIdx.x;
    for (int j = i; j < GG * OUTD; j += 256) g_pool[j] = 0.f;
    if (i < GG) g_cnt[i] = 0.f;
}
__global__ __launch_bounds__(256) void k_final(const int* __restrict__ batch,
                                               const float* __restrict__ Wl,
                                               const float* __restrict__ bl) {
    __shared__ float Ws[DD * OUTD];
    __shared__ float bs[OUTD];
    __shared__ float xs[64 * 68];
    __shared__ int bb[64];
    int tid = threadIdx.x;
    for (int i = tid; i < DD * OUTD; i += 256) Ws[i] = Wl[i];
    if (tid < OUTD) bs[tid] = bl[tid];
    int base = blockIdx.x * 64;
    int warp = tid >> 5, lane = tid & 31;
    for (int t = 0; t < 8; t++) {
        int r = warp * 8 + t;
        int g = base + r;
        float v0 = 0.f, v1 = 0.f;
        if (g < NN) {
            v0 = fmaxf(g_h[(size_t)g * DD + lane], 0.f);
            v1 = fmaxf(g_h[(size_t)g * DD + lane + 32], 0.f);
            if (lane == 0) bb[r] = batch[g];
        }
        xs[r * 68 + lane] = v0;
        xs[r * 68 + lane + 32] = v1;
    }
    __syncthreads();

    int tr = tid >> 4, tc = tid & 15, c0 = tc * 2;
    float acc[4][2];
#pragma unroll
    for (int i = 0; i < 4; i++) { acc[i][0] = bs[c0]; acc[i][1] = bs[c0 + 1]; }
    for (int k = 0; k < DD; k++) {
        float2 w = *(const float2*)&Ws[k * OUTD + c0];
#pragma unroll
        for (int i = 0; i < 4; i++) {
            float xv = xs[(tr + 16 * i) * 68 + k];
            acc[i][0] += xv * w.x; acc[i][1] += xv * w.y;
        }
    }
#pragma unroll
    for (int i = 0; i < 4; i++) {
        int r = tr + 16 * i;
        int g = base + r;
        if (g < NN) red_add_v2(&g_pool[bb[r] * OUTD + c0], acc[i][0], acc[i][1]);
    }
}
__global__ void k_cnt(const int* __restrict__ batch) {
    int i = blockIdx.x * blockDim.x + threadIdx.x;
    if (i < NN) red_add_f(&g_cnt[batch[i]], 1.0f);
}
__global__ void k_out(float* __restrict__ out) {
    int i = blockIdx.x * blockDim.x + threadIdx.x;
    if (i < GG * OUTD) out[i] = g_pool[i] / fmaxf(g_cnt[i / OUTD], 1.0f);
}

extern "C" void kernel_launch(void* const* d_in, const int* in_sizes, int n_in,
                              void* d_out, int out_size) {
    const float* pos    = (const float*)d_in[0];
    const int*   z      = (const int*)d_in[1];
    const int*   ei     = (const int*)d_in[2];
    const int*   batch  = (const int*)d_in[3];
    const float* emb    = (const float*)d_in[4];
    const float* t1_Win = (const float*)d_in[5];
    const float* t1_W1  = (const float*)d_in[6];
    const float* t1_b1  = (const float*)d_in[7];
    const float* t1_W2  = (const float*)d_in[8];
    const float* t1_b2  = (const float*)d_in[9];
    const float* t1_W3  = (const float*)d_in[10];
    const float* t1_b3  = (const float*)d_in[11];
    const float* t2_Win = (const float*)d_in[12];
    const float* t2_W1  = (const float*)d_in[13];
    const float* t2_b1  = (const float*)d_in[14];
    const float* t2_W2  = (const float*)d_in[15];
    const float* t2_b2  = (const float*)d_in[16];
    const float* t2_W3  = (const float*)d_in[17];
    const float* t2_b3  = (const float*)d_in[18];
    const float* Wlin   = (const float*)d_in[19];
    const float* blin   = (const float*)d_in[20];
    float* out = (float*)d_out;

    cudaFuncSetAttribute(k_pq,    cudaFuncAttributeMaxDynamicSharedMemorySize, PQ_SMEM);
    cudaFuncSetAttribute(k_layer, cudaFuncAttributeMaxDynamicSharedMemorySize, LAYER_SMEM);

    const int NT64  = (NN + 63) / 64;
    const int NT128 = (NN + 127) / 128;

    // ---- CSR build (dst-sorted edges) ----
    k_hist_zero<<<(NN + 255) / 256, 256>>>();
    k_hist<<<(EE + 255) / 256, 256>>>(ei);
    k_scan1<<<SCAN_NB, SCAN_B>>>();
    k_scan2<<<1, 128>>>();
    k_scan3<<<SCAN_NB, SCAN_B>>>();
    k_scatter<<<(EE + 255) / 256, 256>>>(pos, ei);

    k_init<<<NT64, 256>>>(pos, z, emb, t1_Win);

    for (int t = 0; t < 2; t++) {
        const float* W1 = t ? t2_W1 : t1_W1;
        const float* b1 = t ? t2_b1 : t1_b1;
        const float* W2 = t ? t2_W2 : t1_W2;
        const float* b2 = t ? t2_b2 : t1_b2;
        const float* W3 = t ? t2_W3 : t1_W3;
        const float* b3 = t ? t2_b3 : t1_b3;
        for (int l = 0; l < NLAY; l++) {
            const float* W1l = W1 + l * 129 * DD;
            k_pq<<<NT128, 256, PQ_SMEM>>>(W1l, b1 + l * DD);
            k_layer<<<NT64, 256, LAYER_SMEM>>>(W2 + l * DD * DD, b2 + l * DD,
                                               W3 + l * 128 * DD, b3 + l * DD,
                                               W1l + 128 * DD);
        }
        if (t == 0) k_proj<<<NT64, 256>>>(t2_Win);
    }

    k_zero_pool<<<1, 256>>>();
    k_final<<<NT64, 256>>>(batch, Wlin, blin);
    k_cnt<<<(NN + 255) / 256, 256>>>(batch);
    k_out<<<(GG * OUTD + 255) / 256, 256>>>(out);
}

// round 6
// speedup vs baseline: 4.5211x; 1.0465x over previous
#include <cuda_runtime.h>
#include <cstddef>
#include <cstdint>

#define NN   100000
#define EE   800000
#define DD   64
#define GG   64
#define OUTD 32
#define FF   61
#define NLAY 4

#define SCAN_B  1024
#define SCAN_NB ((NN + SCAN_B - 1) / SCAN_B)

// ---- device scratch ----
__device__ float g_h[NN * DD];
__device__ float g_p[NN * DD];
__device__ float g_q[NN * DD];
__device__ int   g_deg_i[NN];
__device__ int   g_cur[NN];
__device__ int   g_roff[NN + 1];
__device__ int   g_bsum[SCAN_NB];
__device__ int   g_boff[SCAN_NB];
__device__ int   g_esrc[EE];
__device__ float g_ed2[EE];
__device__ float g_pool[GG * OUTD];
__device__ float g_cnt[GG];

__device__ __forceinline__ void red_add_v2(float* addr, float a, float b) {
    asm volatile("red.global.add.v2.f32 [%0], {%1,%2};"
                 :: "l"(addr), "f"(a), "f"(b) : "memory");
}
__device__ __forceinline__ void red_add_f(float* addr, float a) {
    asm volatile("red.global.add.f32 [%0], %1;" :: "l"(addr), "f"(a) : "memory");
}

// ---- tf32 helpers ----
__device__ __forceinline__ uint32_t f2tf(float x) {
    uint32_t r;
    asm("cvt.rna.tf32.f32 %0, %1;" : "=r"(r) : "f"(x));
    return r;
}
__device__ __forceinline__ void tfsplit(float x, uint32_t& hi, uint32_t& lo) {
    hi = f2tf(x);
    lo = f2tf(x - __uint_as_float(hi));
}
__device__ __forceinline__ void mma8(float* d, const uint32_t* a, uint32_t b0, uint32_t b1) {
    asm("mma.sync.aligned.m16n8k8.row.col.f32.tf32.tf32.f32 "
        "{%0,%1,%2,%3},{%4,%5,%6,%7},{%8,%9},{%0,%1,%2,%3};"
        : "+f"(d[0]), "+f"(d[1]), "+f"(d[2]), "+f"(d[3])
        : "r"(a[0]), "r"(a[1]), "r"(a[2]), "r"(a[3]), "r"(b0), "r"(b1));
}
__device__ __forceinline__ void ldmA(uint32_t* a, uint32_t addr) {
    asm volatile("ldmatrix.sync.aligned.m8n8.x4.shared.b16 {%0,%1,%2,%3},[%4];"
                 : "=r"(a[0]), "=r"(a[1]), "=r"(a[2]), "=r"(a[3]) : "r"(addr));
}
__device__ __forceinline__ uint32_t su(const void* p) {
    return (uint32_t)__cvta_generic_to_shared(p);
}

// Pack weights (row-major W[k][n], leading dim ld, K = K8*8 rows, N = NT*8 cols)
// into fragment order: buf[((kt*NT + nt)*32 + lane)*4] = {hi0, hi1, lo0, lo1}
// where val_j = W[kt*8 + (lane&3) + 4j][nt*8 + lane>>2].
__device__ __forceinline__ void pack_w(uint32_t* buf, const float* __restrict__ W,
                                       int ld, int K8, int NT, int tid, int nthreads) {
    int tot = K8 * NT * 32;
    for (int idx = tid; idx < tot; idx += nthreads) {
        int lane = idx & 31;
        int t = idx >> 5;
        int nt = t % NT, kt = t / NT;
        int k0 = kt * 8 + (lane & 3);
        int n = nt * 8 + (lane >> 2);
        float w0 = W[k0 * ld + n];
        float w1 = W[(k0 + 4) * ld + n];
        uint32_t h0, l0, h1, l1;
        tfsplit(w0, h0, l0);
        tfsplit(w1, h1, l1);
        uint32_t* p = &buf[idx * 4];
        p[0] = h0; p[1] = h1; p[2] = l0; p[3] = l1;
    }
}

// ================= CSR build =================
__global__ void k_hist_zero() {
    int i = blockIdx.x * blockDim.x + threadIdx.x;
    if (i < NN) { g_deg_i[i] = 0; g_cur[i] = 0; }
}
__global__ void k_hist(const int* __restrict__ ei) {
    int e = blockIdx.x * blockDim.x + threadIdx.x;
    if (e < EE) atomicAdd(&g_deg_i[ei[EE + e]], 1);
}
__global__ __launch_bounds__(SCAN_B) void k_scan1() {
    __shared__ int s[SCAN_B];
    int i = blockIdx.x * SCAN_B + threadIdx.x;
    int v = (i < NN) ? g_deg_i[i] : 0;
    s[threadIdx.x] = v;
    __syncthreads();
    for (int off = 1; off < SCAN_B; off <<= 1) {
        int t = (threadIdx.x >= off) ? s[threadIdx.x - off] : 0;
        __syncthreads();
        s[threadIdx.x] += t;
        __syncthreads();
    }
    if (i < NN) g_roff[i] = s[threadIdx.x] - v;
    if (threadIdx.x == SCAN_B - 1) g_bsum[blockIdx.x] = s[threadIdx.x];
}
__global__ __launch_bounds__(128) void k_scan2() {
    __shared__ int s[128];
    int t = threadIdx.x;
    int v = (t < SCAN_NB) ? g_bsum[t] : 0;
    s[t] = v;
    __syncthreads();
    for (int off = 1; off < 128; off <<= 1) {
        int u = (t >= off) ? s[t - off] : 0;
        __syncthreads();
        s[t] += u;
        __syncthreads();
    }
    if (t < SCAN_NB) g_boff[t] = s[t] - v;
    if (t == 127) g_roff[NN] = s[127];
}
__global__ __launch_bounds__(SCAN_B) void k_scan3() {
    int i = blockIdx.x * SCAN_B + threadIdx.x;
    if (i < NN) g_roff[i] += g_boff[blockIdx.x];
}
__global__ void k_scatter(const float* __restrict__ pos, const int* __restrict__ ei) {
    int e = blockIdx.x * blockDim.x + threadIdx.x;
    if (e >= EE) return;
    int s = ei[e], d = ei[EE + e];
    float dx = pos[s * 3 + 0] - pos[d * 3 + 0];
    float dy = pos[s * 3 + 1] - pos[d * 3 + 1];
    float dz = pos[s * 3 + 2] - pos[d * 3 + 2];
    float d2 = dx * dx + dy * dy + dz * dz;
    int p = g_roff[d] + atomicAdd(&g_cur[d], 1);
    g_esrc[p] = s;
    g_ed2[p] = d2;
}

// ================= input / projection (fp32) =================
__global__ __launch_bounds__(256) void k_init(const float* __restrict__ pos,
                                              const int* __restrict__ z,
                                              const float* __restrict__ emb,
                                              const float* __restrict__ Win) {
    __shared__ float Ws[DD * DD];
    __shared__ float xs[64 * 68];
    int tid = threadIdx.x;
    for (int i = tid; i < DD * DD; i += 256) Ws[i] = Win[i];
    int base = blockIdx.x * 64;
    int warp = tid >> 5, lane = tid & 31;
    for (int t = 0; t < 8; t++) {
        int r = warp * 8 + t;
        int g = base + r;
        float v0 = 0.f, v1 = 0.f;
        if (g < NN) {
            int zi = z[g];
            v0 = (lane < 3) ? pos[g * 3 + lane] : emb[zi * FF + lane - 3];
            v1 = emb[zi * FF + lane + 29];
        }
        xs[r * 68 + lane] = v0;
        xs[r * 68 + lane + 32] = v1;
    }
    __syncthreads();
    int tr = tid >> 4, tc = tid & 15, c0 = tc * 4;
    float acc[4][4];
#pragma unroll
    for (int i = 0; i < 4; i++)
#pragma unroll
        for (int j = 0; j < 4; j++) acc[i][j] = 0.f;
    for (int k = 0; k < DD; k++) {
        float4 w = *(const float4*)&Ws[k * DD + c0];
#pragma unroll
        for (int i = 0; i < 4; i++) {
            float xv = xs[(tr + 16 * i) * 68 + k];
            acc[i][0] += xv * w.x; acc[i][1] += xv * w.y;
            acc[i][2] += xv * w.z; acc[i][3] += xv * w.w;
        }
    }
#pragma unroll
    for (int i = 0; i < 4; i++) {
        int g = base + tr + 16 * i;
        if (g < NN)
            *(float4*)&g_h[(size_t)g * DD + c0] =
                make_float4(acc[i][0], acc[i][1], acc[i][2], acc[i][3]);
    }
}

__global__ __launch_bounds__(256) void k_proj(const float* __restrict__ Win) {
    __shared__ float Ws[DD * DD];
    __shared__ float xs[64 * 68];
    int tid = threadIdx.x;
    for (int i = tid; i < DD * DD; i += 256) Ws[i] = Win[i];
    int base = blockIdx.x * 64;
    int warp = tid >> 5, lane = tid & 31;
    for (int t = 0; t < 8; t++) {
        int r = warp * 8 + t;
        int g = base + r;
        float v0 = 0.f, v1 = 0.f;
        if (g < NN) {
            v0 = fmaxf(g_h[(size_t)g * DD + lane], 0.f);
            v1 = fmaxf(g_h[(size_t)g * DD + lane + 32], 0.f);
        }
        xs[r * 68 + lane] = v0;
        xs[r * 68 + lane + 32] = v1;
    }
    __syncthreads();
    int tr = tid >> 4, tc = tid & 15, c0 = tc * 4;
    float acc[4][4];
#pragma unroll
    for (int i = 0; i < 4; i++)
#pragma unroll
        for (int j = 0; j < 4; j++) acc[i][j] = 0.f;
    for (int k = 0; k < DD; k++) {
        float4 w = *(const float4*)&Ws[k * DD + c0];
#pragma unroll
        for (int i = 0; i < 4; i++) {
            float xv = xs[(tr + 16 * i) * 68 + k];
            acc[i][0] += xv * w.x; acc[i][1] += xv * w.y;
            acc[i][2] += xv * w.z; acc[i][3] += xv * w.w;
        }
    }
#pragma unroll
    for (int i = 0; i < 4; i++) {
        int g = base + tr + 16 * i;
        if (g < NN)
            *(float4*)&g_h[(size_t)g * DD + c0] =
                make_float4(acc[i][0], acc[i][1], acc[i][2], acc[i][3]);
    }
}

// ================= k_pq (tensor): p = h@W1a + b1, q = h@W1b =================
// 128-node tile, 256 threads, 8 warps (warp = m16 tile). Two passes (p, q),
// weight buffer reloaded between passes. 3xTF32.
#define PQ_STRIDE 68
#define PQ_SMEM (8192 * 4 + 2 * 128 * PQ_STRIDE * 4 + 64 * 4)
__global__ __launch_bounds__(256) void k_pq(const float* __restrict__ W1,
                                            const float* __restrict__ b1) {
    extern __shared__ uint32_t smu[];
    uint32_t* Wbuf = smu;                       // 8192
    uint32_t* xhi  = Wbuf + 8192;               // 128*68
    uint32_t* xlo  = xhi + 128 * PQ_STRIDE;     // 128*68
    float*    b1s  = (float*)(xlo + 128 * PQ_STRIDE);  // 64

    int tid = threadIdx.x;
    int lane = tid & 31, wid = tid >> 5;
    if (tid < 64) b1s[tid] = b1[tid];

    int base = blockIdx.x * 128;
    // stage h -> hi/lo
    for (int idx = tid; idx < 128 * 16; idx += 256) {
        int r = idx >> 4, cq = (idx & 15) * 4;
        int g = base + r;
        float4 v = make_float4(0.f, 0.f, 0.f, 0.f);
        if (g < NN) v = *(const float4*)&g_h[(size_t)g * DD + cq];
        uint4 hi, lo;
        tfsplit(v.x, hi.x, lo.x); tfsplit(v.y, hi.y, lo.y);
        tfsplit(v.z, hi.z, lo.z); tfsplit(v.w, hi.w, lo.w);
        *(uint4*)&xhi[r * PQ_STRIDE + cq] = hi;
        *(uint4*)&xlo[r * PQ_STRIDE + cq] = lo;
    }
    pack_w(Wbuf, W1, 64, 8, 8, tid, 256);   // W1a (rows 0..63)
    __syncthreads();

    int mt = wid;            // m16 tile index 0..7
    int arow = mt * 16 + (lane & 15);
    int acolo = (lane >> 4) * 4;

    for (int pass = 0; pass < 2; pass++) {
        float d[8][4];
#pragma unroll
        for (int j = 0; j < 8; j++)
#pragma unroll
            for (int c = 0; c < 4; c++) d[j][c] = 0.f;

#pragma unroll
        for (int kt = 0; kt < 8; kt++) {
            uint32_t ah[4], al[4];
            int col = kt * 8 + acolo;
            ldmA(ah, su(&xhi[arow * PQ_STRIDE + col]));
            ldmA(al, su(&xlo[arow * PQ_STRIDE + col]));
#pragma unroll
            for (int j = 0; j < 8; j++) {
                uint4 wv = *(const uint4*)&Wbuf[((kt * 8 + j) * 32 + lane) * 4];
                mma8(d[j], ah, wv.x, wv.y);
                mma8(d[j], al, wv.x, wv.y);
                mma8(d[j], ah, wv.z, wv.w);
            }
        }

        int r0 = base + mt * 16 + (lane >> 2);
        int r1 = r0 + 8;
        if (pass == 0) {
#pragma unroll
            for (int j = 0; j < 8; j++) {
                int col = j * 8 + 2 * (lane & 3);
                float bb0 = b1s[col], bb1 = b1s[col + 1];
                if (r0 < NN) *(float2*)&g_p[(size_t)r0 * DD + col] =
                    make_float2(d[j][0] + bb0, d[j][1] + bb1);
                if (r1 < NN) *(float2*)&g_p[(size_t)r1 * DD + col] =
                    make_float2(d[j][2] + bb0, d[j][3] + bb1);
            }
            __syncthreads();
            pack_w(Wbuf, W1 + 64 * 64, 64, 8, 8, tid, 256);  // W1b
            __syncthreads();
        } else {
#pragma unroll
            for (int j = 0; j < 8; j++) {
                int col = j * 8 + 2 * (lane & 3);
                if (r0 < NN) *(float2*)&g_q[(size_t)r0 * DD + col] =
                    make_float2(d[j][0], d[j][1]);
                if (r1 < NN) *(float2*)&g_q[(size_t)r1 * DD + col] =
                    make_float2(d[j][2], d[j][3]);
            }
        }
    }
}

// ================= k_layer (fused gather + 2 GEMMs, tensor) =================
// x hi/lo: 64 rows x 132 cols (cols 0..63 = h, cols 64..127 = t then agg).
#define LS 132
#define LAYER_SMEM (8192 * 4 + 2 * 64 * LS * 4 + 4 * 64 * 4)
__global__ __launch_bounds__(256) void k_layer(const float* __restrict__ W2,
                                               const float* __restrict__ b2,
                                               const float* __restrict__ W3,
                                               const float* __restrict__ b3,
                                               const float* __restrict__ w1c) {
    extern __shared__ uint32_t smu[];
    uint32_t* Wbuf = smu;                    // 8192
    uint32_t* xhi  = Wbuf + 8192;            // 64*132
    uint32_t* xlo  = xhi + 64 * LS;          // 64*132
    float*    degs = (float*)(xlo + 64 * LS);
    float*    b2s  = degs + 64;
    float*    b3s  = b2s + 64;
    float*    wcs  = b3s + 64;

    int tid = threadIdx.x;
    int lane = tid & 31, wid = tid >> 5;
    if (tid < 64) { b2s[tid] = b2[tid]; b3s[tid] = b3[tid]; wcs[tid] = w1c[tid]; }

    int base = blockIdx.x * 64;
    // stage h -> hi/lo cols 0..63
    for (int idx = tid; idx < 64 * 16; idx += 256) {
        int r = idx >> 4, cq = (idx & 15) * 4;
        int g = base + r;
        float4 v = make_float4(0.f, 0.f, 0.f, 0.f);
        if (g < NN) v = *(const float4*)&g_h[(size_t)g * DD + cq];
        uint4 hi, lo;
        tfsplit(v.x, hi.x, lo.x); tfsplit(v.y, hi.y, lo.y);
        tfsplit(v.z, hi.z, lo.z); tfsplit(v.w, hi.w, lo.w);
        *(uint4*)&xhi[r * LS + cq] = hi;
        *(uint4*)&xlo[r * LS + cq] = lo;
    }
    pack_w(Wbuf, W2, 64, 8, 8, tid, 256);
    __syncthreads();   // wcs + staging ready

    // ---- phase A: CSR gather, 4 threads/node, 16 floats each ----
    {
        int grp = tid >> 2, sub = tid & 3;
        int node = base + grp;
        int cb = sub * 16;
        float ta[16];
#pragma unroll
        for (int j = 0; j < 16; j++) ta[j] = 0.f;
        if (sub == 0) degs[grp] = 0.f;
        if (node < NN) {
            float4 q0 = *(const float4*)&g_q[(size_t)node * DD + cb + 0];
            float4 q1 = *(const float4*)&g_q[(size_t)node * DD + cb + 4];
            float4 q2 = *(const float4*)&g_q[(size_t)node * DD + cb + 8];
            float4 q3 = *(const float4*)&g_q[(size_t)node * DD + cb + 12];
            float4 w0 = *(const float4*)&wcs[cb + 0];
            float4 w1 = *(const float4*)&wcs[cb + 4];
            float4 w2 = *(const float4*)&wcs[cb + 8];
            float4 w3 = *(const float4*)&wcs[cb + 12];
            int r0 = g_roff[node], r1 = g_roff[node + 1];
            if (sub == 0) degs[grp] = (float)(r1 - r0);
            for (int r = r0; r < r1; r++) {
                int s = g_esrc[r];
                float d2 = g_ed2[r];
                const float* pp = &g_p[(size_t)s * DD + cb];
                float4 p0 = *(const float4*)(pp + 0);
                float4 p1 = *(const float4*)(pp + 4);
                float4 p2 = *(const float4*)(pp + 8);
                float4 p3 = *(const float4*)(pp + 12);
                ta[0]  += fmaxf(fmaf(d2, w0.x, p0.x + q0.x), 0.f);
                ta[1]  += fmaxf(fmaf(d2, w0.y, p0.y + q0.y), 0.f);
                ta[2]  += fmaxf(fmaf(d2, w0.z, p0.z + q0.z), 0.f);
                ta[3]  += fmaxf(fmaf(d2, w0.w, p0.w + q0.w), 0.f);
                ta[4]  += fmaxf(fmaf(d2, w1.x, p1.x + q1.x), 0.f);
                ta[5]  += fmaxf(fmaf(d2, w1.y, p1.y + q1.y), 0.f);
                ta[6]  += fmaxf(fmaf(d2, w1.z, p1.z + q1.z), 0.f);
                ta[7]  += fmaxf(fmaf(d2, w1.w, p1.w + q1.w), 0.f);
                ta[8]  += fmaxf(fmaf(d2, w2.x, p2.x + q2.x), 0.f);
                ta[9]  += fmaxf(fmaf(d2, w2.y, p2.y + q2.y), 0.f);
                ta[10] += fmaxf(fmaf(d2, w2.z, p2.z + q2.z), 0.f);
                ta[11] += fmaxf(fmaf(d2, w2.w, p2.w + q2.w), 0.f);
                ta[12] += fmaxf(fmaf(d2, w3.x, p3.x + q3.x), 0.f);
                ta[13] += fmaxf(fmaf(d2, w3.y, p3.y + q3.y), 0.f);
                ta[14] += fmaxf(fmaf(d2, w3.z, p3.z + q3.z), 0.f);
                ta[15] += fmaxf(fmaf(d2, w3.w, p3.w + q3.w), 0.f);
            }
        }
        // split t -> hi/lo into cols 64..127
#pragma unroll
        for (int j = 0; j < 4; j++) {
            uint4 hi, lo;
            tfsplit(ta[4 * j + 0], hi.x, lo.x);
            tfsplit(ta[4 * j + 1], hi.y, lo.y);
            tfsplit(ta[4 * j + 2], hi.z, lo.z);
            tfsplit(ta[4 * j + 3], hi.w, lo.w);
            *(uint4*)&xhi[grp * LS + 64 + cb + 4 * j] = hi;
            *(uint4*)&xlo[grp * LS + 64 + cb + 4 * j] = lo;
        }
    }
    __syncthreads();

    int mt = wid & 3, nh = wid >> 2;          // warp tile: m16 x n32
    int arow = mt * 16 + (lane & 15);
    int acolo = (lane >> 4) * 4;
    int crow = (lane >> 2);                    // c-frag row within m16
    int ccol2 = 2 * (lane & 3);                // c-frag col pair base within n8

    // ---- GEMM1: agg = t @ W2 (+ deg*b2), A = x cols 64..127 ----
    float d[4][4];
#pragma unroll
    for (int j = 0; j < 4; j++)
#pragma unroll
        for (int c = 0; c < 4; c++) d[j][c] = 0.f;
#pragma unroll
    for (int kt = 0; kt < 8; kt++) {
        uint32_t ah[4], al[4];
        int col = 64 + kt * 8 + acolo;
        ldmA(ah, su(&xhi[arow * LS + col]));
        ldmA(al, su(&xlo[arow * LS + col]));
#pragma unroll
        for (int j = 0; j < 4; j++) {
            uint4 wv = *(const uint4*)&Wbuf[((kt * 8 + nh * 4 + j) * 32 + lane) * 4];
            mma8(d[j], ah, wv.x, wv.y);
            mma8(d[j], al, wv.x, wv.y);
            mma8(d[j], ah, wv.z, wv.w);
        }
    }
    __syncthreads();   // everyone done reading t-cols + Wbuf(W2)

    // write agg hi/lo into cols 64..127 (overwriting t)
    {
        int row0 = mt * 16 + crow, row1 = row0 + 8;
        float dg0 = degs[row0], dg1 = degs[row1];
#pragma unroll
        for (int j = 0; j < 4; j++) {
            int col = nh * 32 + j * 8 + ccol2;
            float b0 = b2s[col], b1v = b2s[col + 1];
            float a0 = fmaf(dg0, b0, d[j][0]);
            float a1 = fmaf(dg0, b1v, d[j][1]);
            float a2 = fmaf(dg1, b0, d[j][2]);
            float a3 = fmaf(dg1, b1v, d[j][3]);
            uint2 h0, l0, h1, l1;
            tfsplit(a0, h0.x, l0.x); tfsplit(a1, h0.y, l0.y);
            tfsplit(a2, h1.x, l1.x); tfsplit(a3, h1.y, l1.y);
            *(uint2*)&xhi[row0 * LS + 64 + col] = h0;
            *(uint2*)&xlo[row0 * LS + 64 + col] = l0;
            *(uint2*)&xhi[row1 * LS + 64 + col] = h1;
            *(uint2*)&xlo[row1 * LS + 64 + col] = l1;
        }
    }
    pack_w(Wbuf, W3, 64, 8, 8, tid, 256);     // W3 rows 0..63
    __syncthreads();

    // ---- GEMM2: h += relu([h, agg] @ W3 + b3), split into two K=64 halves ----
#pragma unroll
    for (int j = 0; j < 4; j++) {
        int col = nh * 32 + j * 8 + ccol2;
        d[j][0] = b3s[col]; d[j][1] = b3s[col + 1];
        d[j][2] = b3s[col]; d[j][3] = b3s[col + 1];
    }
    // half A: h (cols 0..63) with W3 rows 0..63
#pragma unroll
    for (int kt = 0; kt < 8; kt++) {
        uint32_t ah[4], al[4];
        int col = kt * 8 + acolo;
        ldmA(ah, su(&xhi[arow * LS + col]));
        ldmA(al, su(&xlo[arow * LS + col]));
#pragma unroll
        for (int j = 0; j < 4; j++) {
            uint4 wv = *(const uint4*)&Wbuf[((kt * 8 + nh * 4 + j) * 32 + lane) * 4];
            mma8(d[j], ah, wv.x, wv.y);
            mma8(d[j], al, wv.x, wv.y);
            mma8(d[j], ah, wv.z, wv.w);
        }
    }
    __syncthreads();
    pack_w(Wbuf, W3 + 64 * 64, 64, 8, 8, tid, 256);  // W3 rows 64..127
    __syncthreads();
    // half B: agg (cols 64..127) with W3 rows 64..127
#pragma unroll
    for (int kt = 0; kt < 8; kt++) {
        uint32_t ah[4], al[4];
        int col = 64 + kt * 8 + acolo;
        ldmA(ah, su(&xhi[arow * LS + col]));
        ldmA(al, su(&xlo[arow * LS + col]));
#pragma unroll
        for (int j = 0; j < 4; j++) {
            uint4 wv = *(const uint4*)&Wbuf[((kt * 8 + nh * 4 + j) * 32 + lane) * 4];
            mma8(d[j], ah, wv.x, wv.y);
            mma8(d[j], al, wv.x, wv.y);
            mma8(d[j], ah, wv.z, wv.w);
        }
    }

    // epilogue: h += relu(d)
    {
        int r0 = base + mt * 16 + crow;
        int r1 = r0 + 8;
#pragma unroll
        for (int j = 0; j < 4; j++) {
            int col = nh * 32 + j * 8 + ccol2;
            if (r0 < NN) {
                float2 h0 = *(const float2*)&g_h[(size_t)r0 * DD + col];
                *(float2*)&g_h[(size_t)r0 * DD + col] =
                    make_float2(h0.x + fmaxf(d[j][0], 0.f), h0.y + fmaxf(d[j][1], 0.f));
            }
            if (r1 < NN) {
                float2 h1 = *(const float2*)&g_h[(size_t)r1 * DD + col];
                *(float2*)&g_h[(size_t)r1 * DD + col] =
                    make_float2(h1.x + fmaxf(d[j][2], 0.f), h1.y + fmaxf(d[j][3], 0.f));
            }
        }
    }
}

// ================= final linear + pool =================
__global__ void k_zero_pool() {
    int i = threadIdx.x;
    for (int j = i; j < GG * OUTD; j += 256) g_pool[j] = 0.f;
    if (i < GG) g_cnt[i] = 0.f;
}
__global__ __launch_bounds__(256) void k_final(const int* __restrict__ batch,
                                               const float* __restrict__ Wl,
                                               const float* __restrict__ bl) {
    __shared__ float Ws[DD * OUTD];
    __shared__ float bs[OUTD];
    __shared__ float xs[64 * 68];
    __shared__ int bb[64];
    int tid = threadIdx.x;
    for (int i = tid; i < DD * OUTD; i += 256) Ws[i] = Wl[i];
    if (tid < OUTD) bs[tid] = bl[tid];
    int base = blockIdx.x * 64;
    int warp = tid >> 5, lane = tid & 31;
    for (int t = 0; t < 8; t++) {
        int r = warp * 8 + t;
        int g = base + r;
        float v0 = 0.f, v1 = 0.f;
        if (g < NN) {
            v0 = fmaxf(g_h[(size_t)g * DD + lane], 0.f);
            v1 = fmaxf(g_h[(size_t)g * DD + lane + 32], 0.f);
            if (lane == 0) bb[r] = batch[g];
        }
        xs[r * 68 + lane] = v0;
        xs[r * 68 + lane + 32] = v1;
    }
    __syncthreads();

    int tr = tid >> 4, tc = tid & 15, c0 = tc * 2;
    float acc[4][2];
#pragma unroll
    for (int i = 0; i < 4; i++) { acc[i][0] = bs[c0]; acc[i][1] = bs[c0 + 1]; }
    for (int k = 0; k < DD; k++) {
        float2 w = *(const float2*)&Ws[k * OUTD + c0];
#pragma unroll
        for (int i = 0; i < 4; i++) {
            float xv = xs[(tr + 16 * i) * 68 + k];
            acc[i][0] += xv * w.x; acc[i][1] += xv * w.y;
        }
    }
#pragma unroll
    for (int i = 0; i < 4; i++) {
        int r = tr + 16 * i;
        int g = base + r;
        if (g < NN) red_add_v2(&g_pool[bb[r] * OUTD + c0], acc[i][0], acc[i][1]);
    }
}
__global__ void k_cnt(const int* __restrict__ batch) {
    int i = blockIdx.x * blockDim.x + threadIdx.x;
    if (i < NN) red_add_f(&g_cnt[batch[i]], 1.0f);
}
__global__ void k_out(float* __restrict__ out) {
    int i = blockIdx.x * blockDim.x + threadIdx.x;
    if (i < GG * OUTD) out[i] = g_pool[i] / fmaxf(g_cnt[i / OUTD], 1.0f);
}

extern "C" void kernel_launch(void* const* d_in, const int* in_sizes, int n_in,
                              void* d_out, int out_size) {
    const float* pos    = (const float*)d_in[0];
    const int*   z      = (const int*)d_in[1];
    const int*   ei     = (const int*)d_in[2];
    const int*   batch  = (const int*)d_in[3];
    const float* emb    = (const float*)d_in[4];
    const float* t1_Win = (const float*)d_in[5];
    const float* t1_W1  = (const float*)d_in[6];
    const float* t1_b1  = (const float*)d_in[7];
    const float* t1_W2  = (const float*)d_in[8];
    const float* t1_b2  = (const float*)d_in[9];
    const float* t1_W3  = (const float*)d_in[10];
    const float* t1_b3  = (const float*)d_in[11];
    const float* t2_Win = (const float*)d_in[12];
    const float* t2_W1  = (const float*)d_in[13];
    const float* t2_b1  = (const float*)d_in[14];
    const float* t2_W2  = (const float*)d_in[15];
    const float* t2_b2  = (const float*)d_in[16];
    const float* t2_W3  = (const float*)d_in[17];
    const float* t2_b3  = (const float*)d_in[18];
    const float* Wlin   = (const float*)d_in[19];
    const float* blin   = (const float*)d_in[20];
    float* out = (float*)d_out;

    cudaFuncSetAttribute(k_pq,    cudaFuncAttributeMaxDynamicSharedMemorySize, PQ_SMEM);
    cudaFuncSetAttribute(k_layer, cudaFuncAttributeMaxDynamicSharedMemorySize, LAYER_SMEM);

    const int NT64  = (NN + 63) / 64;
    const int NT128 = (NN + 127) / 128;

    // ---- CSR build ----
    k_hist_zero<<<(NN + 255) / 256, 256>>>();
    k_hist<<<(EE + 255) / 256, 256>>>(ei);
    k_scan1<<<SCAN_NB, SCAN_B>>>();
    k_scan2<<<1, 128>>>();
    k_scan3<<<SCAN_NB, SCAN_B>>>();
    k_scatter<<<(EE + 255) / 256, 256>>>(pos, ei);

    k_init<<<NT64, 256>>>(pos, z, emb, t1_Win);

    for (int t = 0; t < 2; t++) {
        const float* W1 = t ? t2_W1 : t1_W1;
        const float* b1 = t ? t2_b1 : t1_b1;
        const float* W2 = t ? t2_W2 : t1_W2;
        const float* b2 = t ? t2_b2 : t1_b2;
        const float* W3 = t ? t2_W3 : t1_W3;
        const float* b3 = t ? t2_b3 : t1_b3;
        for (int l = 0; l < NLAY; l++) {
            const float* W1l = W1 + l * 129 * DD;
            k_pq<<<NT128, 256, PQ_SMEM>>>(W1l, b1 + l * DD);
            k_layer<<<NT64, 256, LAYER_SMEM>>>(W2 + l * DD * DD, b2 + l * DD,
                                               W3 + l * 128 * DD, b3 + l * DD,
                                               W1l + 128 * DD);
        }
        if (t == 0) k_proj<<<NT64, 256>>>(t2_Win);
    }

    k_zero_pool<<<1, 256>>>();
    k_final<<<NT64, 256>>>(batch, Wlin, blin);
    k_cnt<<<(NN + 255) / 256, 256>>>(batch);
    k_out<<<(GG * OUTD + 255) / 256, 256>>>(out);
}